// round 1
// baseline (speedup 1.0000x reference)
#include <cuda_runtime.h>
#include <cuda_bf16.h>
#include <cstdint>

// COO SpMM: out[i,:] = sum_{e: rows[e]==i} vals[e] * embeds[cols[e],:]
// N=100000, E=1600000, D=48 (= 12 float4)

#define N_NODES 100000
#define N_EDGES 1600000
#define D_FEAT  48
#define D_VEC4  (D_FEAT / 4)   // 12

__global__ void zero_out_kernel(float4* __restrict__ out4, int n4) {
    int i = blockIdx.x * blockDim.x + threadIdx.x;
    if (i < n4) out4[i] = make_float4(0.f, 0.f, 0.f, 0.f);
}

__device__ __forceinline__ void red_add_v4(float* ptr, float4 v) {
    asm volatile("red.global.add.v4.f32 [%0], {%1, %2, %3, %4};"
                 :: "l"(ptr), "f"(v.x), "f"(v.y), "f"(v.z), "f"(v.w)
                 : "memory");
}

__global__ void __launch_bounds__(256)
spmm_coo_kernel(const int* __restrict__ rows,
                const int* __restrict__ cols,
                const float* __restrict__ vals,
                const float4* __restrict__ embeds4,  // [N, 12] float4
                float* __restrict__ out,             // [N, 48] float
                int n_edges) {
    int e = blockIdx.x * blockDim.x + threadIdx.x;
    if (e >= n_edges) return;

    int r = rows[e];
    int c = cols[e];
    float v = vals[e];

    const float4* src = embeds4 + (size_t)c * D_VEC4;
    float* dst = out + (size_t)r * D_FEAT;

    // Gather all 12 float4 first (MLP=12, hides L2-hit latency), then scatter.
    float4 x[D_VEC4];
#pragma unroll
    for (int i = 0; i < D_VEC4; i++) x[i] = __ldg(&src[i]);

#pragma unroll
    for (int i = 0; i < D_VEC4; i++) {
        float4 m = make_float4(v * x[i].x, v * x[i].y, v * x[i].z, v * x[i].w);
        red_add_v4(dst + i * 4, m);
    }
}

extern "C" void kernel_launch(void* const* d_in, const int* in_sizes, int n_in,
                              void* d_out, int out_size) {
    const int*    rows   = (const int*)d_in[0];
    const int*    cols   = (const int*)d_in[1];
    const float*  vals   = (const float*)d_in[2];
    const float4* embeds = (const float4*)d_in[3];
    float* out = (float*)d_out;

    int n_edges = in_sizes[0];
    int n_out4  = out_size / 4;   // 100000*48/4 = 1.2M float4

    zero_out_kernel<<<(n_out4 + 255) / 256, 256>>>((float4*)out, n_out4);
    spmm_coo_kernel<<<(n_edges + 255) / 256, 256>>>(rows, cols, vals, embeds, out, n_edges);
}

// round 2
// speedup vs baseline: 1.9864x; 1.9864x over previous
#include <cuda_runtime.h>
#include <cuda_bf16.h>
#include <cstdint>

// COO SpMM via on-the-fly CSR build, then row-gather (no atomics in main kernel).
// out[i,:] = sum_{e: rows[e]==i} vals[e] * embeds[cols[e],:]

#define N_NODES 100000
#define N_EDGES 1600000
#define D_FEAT  48

#define SCAN_N   (N_NODES + 1)          // 100001
#define SCAN_BLK 1024
#define SCAN_NB  ((SCAN_N + SCAN_BLK - 1) / SCAN_BLK)   // 98

// Scratch (static device globals; allocation-free)
__device__ int   g_counts[SCAN_N];
__device__ int   g_offs[SCAN_N];
__device__ int   g_cursor[N_NODES];
__device__ int   g_bsums[128];
__device__ int2  g_edges[N_EDGES];      // {col, val_as_int}

// ---------- pass 0: zero histogram ----------
__global__ void zero_counts_kernel() {
    int i = blockIdx.x * blockDim.x + threadIdx.x;
    if (i < SCAN_N) g_counts[i] = 0;
}

// ---------- pass 1: histogram of rows ----------
__global__ void hist_kernel(const int* __restrict__ rows, int n) {
    int e = blockIdx.x * blockDim.x + threadIdx.x;
    if (e < n) atomicAdd(&g_counts[rows[e]], 1);
}

// ---------- pass 2a: per-block exclusive scan ----------
__global__ void scan_pass1() {
    __shared__ int warp_sums[32];
    int i = blockIdx.x * SCAN_BLK + threadIdx.x;
    int v = (i < SCAN_N) ? g_counts[i] : 0;
    int lane = threadIdx.x & 31, wid = threadIdx.x >> 5;

    int inc = v;
#pragma unroll
    for (int d = 1; d < 32; d <<= 1) {
        int t = __shfl_up_sync(0xffffffffu, inc, d);
        if (lane >= d) inc += t;
    }
    if (lane == 31) warp_sums[wid] = inc;
    __syncthreads();
    if (wid == 0) {
        int s = warp_sums[lane];
#pragma unroll
        for (int d = 1; d < 32; d <<= 1) {
            int t = __shfl_up_sync(0xffffffffu, s, d);
            if (lane >= d) s += t;
        }
        warp_sums[lane] = s;
    }
    __syncthreads();
    int base = (wid > 0) ? warp_sums[wid - 1] : 0;
    if (i < SCAN_N) g_offs[i] = base + inc - v;      // exclusive within block
    if (threadIdx.x == SCAN_BLK - 1) g_bsums[blockIdx.x] = warp_sums[31];
}

// ---------- pass 2b: scan block sums (single block, nb<=128) ----------
__global__ void scan_pass2() {
    __shared__ int sh[128];
    int v = (threadIdx.x < SCAN_NB) ? g_bsums[threadIdx.x] : 0;
    sh[threadIdx.x] = v;
    __syncthreads();
    for (int d = 1; d < 128; d <<= 1) {
        int t = (threadIdx.x >= d) ? sh[threadIdx.x - d] : 0;
        __syncthreads();
        sh[threadIdx.x] += t;
        __syncthreads();
    }
    if (threadIdx.x < SCAN_NB) g_bsums[threadIdx.x] = sh[threadIdx.x] - v;  // exclusive
}

// ---------- pass 2c: add block bases, init cursor ----------
__global__ void scan_pass3() {
    int i = blockIdx.x * SCAN_BLK + threadIdx.x;
    if (i < SCAN_N) {
        int val = g_offs[i] + g_bsums[blockIdx.x];
        g_offs[i] = val;
        if (i < N_NODES) g_cursor[i] = val;
    }
}

// ---------- pass 3: scatter edges into CSR bins ----------
__global__ void scatter_kernel(const int* __restrict__ rows,
                               const int* __restrict__ cols,
                               const float* __restrict__ vals, int n) {
    int e = blockIdx.x * blockDim.x + threadIdx.x;
    if (e < n) {
        int r = rows[e];
        int p = atomicAdd(&g_cursor[r], 1);
        g_edges[p] = make_int2(cols[e], __float_as_int(vals[e]));
    }
}

// ---------- pass 4: row-gather SpMM (16 lanes per row) ----------
__global__ void __launch_bounds__(256)
spmm_csr_kernel(const float* __restrict__ embeds, float* __restrict__ out) {
    int row  = blockIdx.x * 16 + (threadIdx.x >> 4);
    int lane = threadIdx.x & 15;
    if (row >= N_NODES) return;

    int s = g_offs[row];
    int t = g_offs[row + 1];

    float a0 = 0.f, a1 = 0.f, a2 = 0.f;
    int e = s;
    for (; e + 2 <= t; e += 2) {
        int2 p0 = __ldg(&g_edges[e]);
        int2 p1 = __ldg(&g_edges[e + 1]);
        const float* b0 = embeds + (size_t)p0.x * D_FEAT + lane;
        const float* b1 = embeds + (size_t)p1.x * D_FEAT + lane;
        float x0 = __ldg(b0), x1 = __ldg(b0 + 16), x2 = __ldg(b0 + 32);
        float y0 = __ldg(b1), y1 = __ldg(b1 + 16), y2 = __ldg(b1 + 32);
        float v0 = __int_as_float(p0.y);
        float v1 = __int_as_float(p1.y);
        a0 += v0 * x0; a1 += v0 * x1; a2 += v0 * x2;
        a0 += v1 * y0; a1 += v1 * y1; a2 += v1 * y2;
    }
    if (e < t) {
        int2 p = __ldg(&g_edges[e]);
        const float* b = embeds + (size_t)p.x * D_FEAT + lane;
        float v = __int_as_float(p.y);
        a0 += v * __ldg(b); a1 += v * __ldg(b + 16); a2 += v * __ldg(b + 32);
    }

    float* o = out + (size_t)row * D_FEAT + lane;
    o[0] = a0; o[16] = a1; o[32] = a2;
}

extern "C" void kernel_launch(void* const* d_in, const int* in_sizes, int n_in,
                              void* d_out, int out_size) {
    const int*   rows   = (const int*)d_in[0];
    const int*   cols   = (const int*)d_in[1];
    const float* vals   = (const float*)d_in[2];
    const float* embeds = (const float*)d_in[3];
    float* out = (float*)d_out;

    int n_edges = in_sizes[0];

    zero_counts_kernel<<<(SCAN_N + 255) / 256, 256>>>();
    hist_kernel<<<(n_edges + 255) / 256, 256>>>(rows, n_edges);
    scan_pass1<<<SCAN_NB, SCAN_BLK>>>();
    scan_pass2<<<1, 128>>>();
    scan_pass3<<<SCAN_NB, SCAN_BLK>>>();
    scatter_kernel<<<(n_edges + 255) / 256, 256>>>(rows, cols, vals, n_edges);
    spmm_csr_kernel<<<(N_NODES + 15) / 16, 256>>>(embeds, out);
}